// round 16
// baseline (speedup 1.0000x reference)
#include <cuda_runtime.h>
#include <cuda.h>
#include <cuda_fp16.h>
#include <math.h>
#include <stdint.h>

#define T_TOK 2048
#define NH    32
#define NKV   8
#define HD    128
#define GQA   4
#define BM    64
#define BN    64
#define NTH   128          // 4 warps: warp = rowg*2 + colg
#define ATTN_SCALE 0.08838834764831845f
#define CEXP2 0.1275187815175719f   // ATTN_SCALE * log2(e)

// ---- pre-converted fp16 copies of K/V, head-major ----
__device__ __half gK[(size_t)NKV * T_TOK * HD];
__device__ __half gV[(size_t)NKV * T_TOK * HD];

// smem: 3 KV stages (32KB each), 2 P buffers (8KB), mbarriers, l-buffer
#define STG_BYTES 32768
#define PB_OFF    98304      // + buf*8192
#define MB_OFF    114688     // 3 x (full,empty) = 48B
#define LB_OFF    114752     // 128 floats
#define SMEM_BYTES 115264

__device__ __forceinline__ uint32_t smem_u32(const void* p) {
    return (uint32_t)__cvta_generic_to_shared(p);
}
// swizzled byte offset of 16B chunk (row, chunk) in TMA SW128 half-tiles
__device__ __forceinline__ uint32_t swT(int row, int c) {
    return (uint32_t)(((c >> 3) << 13) + (row << 7) + ((((c & 7) ^ (row & 7))) << 4));
}
__device__ __forceinline__ void ldsm4(uint32_t (&r)[4], uint32_t a) {
    asm volatile("ldmatrix.sync.aligned.m8n8.x4.shared.b16 {%0,%1,%2,%3}, [%4];"
                 : "=r"(r[0]), "=r"(r[1]), "=r"(r[2]), "=r"(r[3]) : "r"(a));
}
__device__ __forceinline__ void ldsm4t(uint32_t (&r)[4], uint32_t a) {
    asm volatile("ldmatrix.sync.aligned.m8n8.x4.trans.shared.b16 {%0,%1,%2,%3}, [%4];"
                 : "=r"(r[0]), "=r"(r[1]), "=r"(r[2]), "=r"(r[3]) : "r"(a));
}
__device__ __forceinline__ void stsm4(uint32_t a, const uint32_t (&r)[4]) {
    asm volatile("stmatrix.sync.aligned.m8n8.x4.shared.b16 [%0], {%1,%2,%3,%4};"
                 :: "r"(a), "r"(r[0]), "r"(r[1]), "r"(r[2]), "r"(r[3]) : "memory");
}
__device__ __forceinline__ void mma16816(float (&d)[4], const uint32_t (&a)[4],
                                         uint32_t b0, uint32_t b1) {
    asm volatile(
        "mma.sync.aligned.m16n8k16.row.col.f32.f16.f16.f32 "
        "{%0,%1,%2,%3}, {%4,%5,%6,%7}, {%8,%9}, {%0,%1,%2,%3};"
        : "+f"(d[0]), "+f"(d[1]), "+f"(d[2]), "+f"(d[3])
        : "r"(a[0]), "r"(a[1]), "r"(a[2]), "r"(a[3]), "r"(b0), "r"(b1));
}
__device__ __forceinline__ uint32_t pack_f2(float x, float y) {
    __half2 hh = __float22half2_rn(make_float2(x, y));
    return *reinterpret_cast<uint32_t*>(&hh);
}
__device__ __forceinline__ void mbar_init(uint32_t a, uint32_t cnt) {
    asm volatile("mbarrier.init.shared.b64 [%0], %1;" :: "r"(a), "r"(cnt) : "memory");
}
__device__ __forceinline__ void mbar_arrive(uint32_t a) {
    asm volatile("mbarrier.arrive.shared.b64 _, [%0];" :: "r"(a) : "memory");
}
__device__ __forceinline__ void mbar_expect_tx(uint32_t a, uint32_t tx) {
    asm volatile("mbarrier.arrive.expect_tx.shared.b64 _, [%0], %1;"
                 :: "r"(a), "r"(tx) : "memory");
}
__device__ __forceinline__ void mwait(uint32_t mbar, int phase) {
    asm volatile(
        "{\n\t.reg .pred P;\n"
        "W1_%=:\n\t"
        "mbarrier.try_wait.parity.acquire.cta.shared::cta.b64 P, [%0], %1, 10000000;\n\t"
        "@P bra W2_%=;\n\t"
        "bra W1_%=;\n"
        "W2_%=:\n\t}"
        :: "r"(mbar), "r"((uint32_t)phase) : "memory");
}
__device__ __forceinline__ void tma3d(uint32_t dst, const CUtensorMap* m,
                                      int x, int y, int z, uint32_t mbar) {
    asm volatile(
        "cp.async.bulk.tensor.3d.shared::cta.global.tile.mbarrier::complete_tx::bytes "
        "[%0], [%1, {%2, %3, %4}], [%5];"
        :: "r"(dst), "l"(m), "r"(x), "r"(y), "r"(z), "r"(mbar) : "memory");
}
__device__ __forceinline__ void named_bar(int id) {
    asm volatile("bar.sync %0, 64;" :: "r"(id) : "memory");
}

// ---- pre-pass: K/V fp32 -> fp16, head-major ----
__global__ __launch_bounds__(256)
void cvt_kernel(const float* __restrict__ k, const float* __restrict__ v) {
    const int NK4 = T_TOK * NKV * 32;
    int idx = blockIdx.x * 256 + threadIdx.x;
    const float* src;
    __half* dst;
    if (idx < NK4) { src = k; dst = gK; }
    else if (idx < 2 * NK4) { idx -= NK4; src = v; dst = gV; }
    else return;
    int d4 = idx & 31;
    int hh = (idx >> 5) & 7;
    int t  = idx >> 8;
    float4 f = *reinterpret_cast<const float4*>(
        src + ((size_t)t * NKV + hh) * HD + d4 * 4);
    uint32_t w0 = pack_f2(f.x, f.y);
    uint32_t w1 = pack_f2(f.z, f.w);
    size_t o = ((size_t)hh * T_TOK + t) * HD + d4 * 4;
    *reinterpret_cast<uint2*>(dst + o) = make_uint2(w0, w1);
}

__global__ __launch_bounds__(NTH, 2)
void attn_mma_kernel(const __grid_constant__ CUtensorMap mapK,
                     const __grid_constant__ CUtensorMap mapV,
                     const float* __restrict__ q, float* __restrict__ out) {
    extern __shared__ char sm[];
    const uint32_t sB = smem_u32(sm);

    const int qt  = (int)gridDim.x - 1 - (int)blockIdx.x;  // heavy tiles first
    const int hh  = blockIdx.y;
    const int kvh = hh / GQA;
    const int q0  = qt * BM;
    const int nt  = qt + 1;

    const int tid  = threadIdx.x;
    const int lane = tid & 31;
    const int warp = tid >> 5;
    const int rowg = warp >> 1;           // 0/1: rows [rowg*32, +32)
    const int colg = warp & 1;            // 0/1: S cols [colg*32, +32), O cols [colg*64, +64)
    const int gid  = lane >> 2;
    const int tig  = lane & 3;
    const int rbaseL = rowg * 32;

    // lane patterns
    const int rowK = ((lane >> 4) << 3) + (lane & 7);     // B (K) ldsm rows
    const int cK   = (lane >> 3) & 1;
    const int rowV = ((lane >> 3) & 1) * 8 + (lane & 7);  // B (V) ldsm.trans rows
    const int cV   = lane >> 4;
    const int rowP = lane & 15;                           // A (P) ldsm rows
    const int cP   = lane >> 4;
    const int rowS = (lane & 7) + ((lane >> 3) & 1) * 8;  // stmatrix rows
    const int cS   = lane >> 4;

    auto mbF = [&](int s) { return sB + MB_OFF + (uint32_t)s * 16; };
    auto mbE = [&](int s) { return sB + MB_OFF + (uint32_t)s * 16 + 8; };

    if (tid == 0) {
        #pragma unroll
        for (int s = 0; s < 3; s++) { mbar_init(mbF(s), 1); mbar_init(mbE(s), 4); }
        asm volatile("fence.proxy.async.shared::cta;" ::: "memory");
    }
    __syncthreads();

    auto issue_tile = [&](int j, int s) {
        uint32_t full = mbF(s);
        mbar_expect_tx(full, STG_BYTES);
        uint32_t base = sB + (uint32_t)s * STG_BYTES;
        tma3d(base,         &mapK,  0, j * BN, kvh, full);
        tma3d(base + 8192,  &mapK, 64, j * BN, kvh, full);
        tma3d(base + 16384, &mapV,  0, j * BN, kvh, full);
        tma3d(base + 24576, &mapV, 64, j * BN, kvh, full);
    };
    if (tid == 0) {
        int npre = nt < 3 ? nt : 3;
        for (int j = 0; j < npre; j++) issue_tile(j, j);
    }

    // ---- Q fragments: rows [q0+rowg*32, +32), full K=128, in registers
    uint32_t qf[2][8][4];
    #pragma unroll
    for (int f = 0; f < 2; f++)
        #pragma unroll
        for (int h2 = 0; h2 < 2; h2++) {
            const float* p = q + ((size_t)(q0 + rbaseL + f * 16 + h2 * 8 + gid) * NH
                                  + hh) * HD + tig * 2;
            #pragma unroll
            for (int kk = 0; kk < 8; kk++) {
                float2 lo = *reinterpret_cast<const float2*>(p + kk * 16);
                float2 hi = *reinterpret_cast<const float2*>(p + kk * 16 + 8);
                qf[f][kk][h2]     = pack_f2(lo.x, lo.y);
                qf[f][kk][2 + h2] = pack_f2(hi.x, hi.y);
            }
        }

    float o[2][8][4];
    #pragma unroll
    for (int f = 0; f < 2; f++)
        #pragma unroll
        for (int g = 0; g < 8; g++)
            #pragma unroll
            for (int c = 0; c < 4; c++) o[f][g][c] = 0.f;
    float l[4] = {0.f, 0.f, 0.f, 0.f};
    uint32_t aPrev[2][2][4];     // own-half P(kt-1) A-fragments

    // softmax: s -> aPrev + stmatrix into P buffer (kt&1), accumulate l
    auto softmax_store = [&](float (&s)[2][4][4], int kt) {
        const bool diag = (kt == nt - 1);
        const int n0 = kt * BN + colg * 32;
        const uint32_t Pw = sB + PB_OFF + (uint32_t)(kt & 1) * 8192;
        #pragma unroll
        for (int f = 0; f < 2; f++) {
            const int r0 = q0 + rbaseL + f * 16 + gid;
            const int r1 = r0 + 8;
            float pv[4][4];
            #pragma unroll
            for (int g = 0; g < 4; g++) {
                int c0 = n0 + g * 8 + tig * 2;
                float p0 = exp2f(s[f][g][0] * CEXP2);
                float p1 = exp2f(s[f][g][1] * CEXP2);
                float p2 = exp2f(s[f][g][2] * CEXP2);
                float p3 = exp2f(s[f][g][3] * CEXP2);
                if (diag) {
                    if (c0     > r0) p0 = 0.f;
                    if (c0 + 1 > r0) p1 = 0.f;
                    if (c0     > r1) p2 = 0.f;
                    if (c0 + 1 > r1) p3 = 0.f;
                }
                l[f * 2 + 0] += p0 + p1;
                l[f * 2 + 1] += p2 + p3;
                pv[g][0] = p0; pv[g][1] = p1; pv[g][2] = p2; pv[g][3] = p3;
            }
            #pragma unroll
            for (int kc = 0; kc < 2; kc++) {
                aPrev[f][kc][0] = pack_f2(pv[2 * kc][0],     pv[2 * kc][1]);
                aPrev[f][kc][1] = pack_f2(pv[2 * kc][2],     pv[2 * kc][3]);
                aPrev[f][kc][2] = pack_f2(pv[2 * kc + 1][0], pv[2 * kc + 1][1]);
                aPrev[f][kc][3] = pack_f2(pv[2 * kc + 1][2], pv[2 * kc + 1][3]);
                stsm4(Pw + swT(rbaseL + f * 16 + rowS, colg * 4 + kc * 2 + cS),
                      aPrev[f][kc]);
            }
        }
        named_bar(1 + rowg);
    };

    int kS = 0, kP = 0, pP = 0;

    // ---- peeled kt=0: GEMM1 only
    {
        mwait(mbF(0), 0);
        const uint32_t bK = sB;
        float s[2][4][4];
        #pragma unroll
        for (int f = 0; f < 2; f++)
            #pragma unroll
            for (int g = 0; g < 4; g++)
                #pragma unroll
                for (int c = 0; c < 4; c++) s[f][g][c] = 0.f;
        #pragma unroll
        for (int kk = 0; kk < 8; kk++) {
            uint32_t kb[2][4];
            #pragma unroll
            for (int n = 0; n < 2; n++)
                ldsm4(kb[n], bK + swT(colg * 32 + n * 16 + rowK, 2 * kk + cK));
            #pragma unroll
            for (int f = 0; f < 2; f++)
                #pragma unroll
                for (int n = 0; n < 2; n++) {
                    mma16816(s[f][2 * n],     qf[f][kk], kb[n][0], kb[n][1]);
                    mma16816(s[f][2 * n + 1], qf[f][kk], kb[n][2], kb[n][3]);
                }
        }
        softmax_store(s, 0);
        kS = 1;
    }

    // ---- main loop: iter kt = GEMM1(kt) + GEMM2(kt-1)
    for (int kt = 1; kt < nt; kt++) {
        mwait(mbF(kS), kP);
        const int vS = (kS == 0) ? 2 : kS - 1;
        const uint32_t bK = sB + (uint32_t)kS * STG_BYTES;
        const uint32_t bV = sB + (uint32_t)vS * STG_BYTES + 16384 + (uint32_t)colg * 8192;
        const uint32_t Pr = sB + PB_OFF + (uint32_t)((kt - 1) & 1) * 8192;

        float s[2][4][4];
        #pragma unroll
        for (int f = 0; f < 2; f++)
            #pragma unroll
            for (int g = 0; g < 4; g++)
                #pragma unroll
                for (int c = 0; c < 4; c++) s[f][g][c] = 0.f;

        #pragma unroll
        for (int kk = 0; kk < 8; kk++) {
            uint32_t kb[2][4];
            #pragma unroll
            for (int n = 0; n < 2; n++)
                ldsm4(kb[n], bK + swT(colg * 32 + n * 16 + rowK, 2 * kk + cK));
            #pragma unroll
            for (int f = 0; f < 2; f++)
                #pragma unroll
                for (int n = 0; n < 2; n++) {
                    mma16816(s[f][2 * n],     qf[f][kk], kb[n][0], kb[n][1]);
                    mma16816(s[f][2 * n + 1], qf[f][kk], kb[n][2], kb[n][3]);
                }
            if (kk & 1) {
                const int K2 = kk >> 1;            // GEMM2 k-chunk (16 tokens)
                uint32_t aF[2][4];
                if ((K2 >> 1) == colg) {
                    #pragma unroll
                    for (int f = 0; f < 2; f++)
                        #pragma unroll
                        for (int r = 0; r < 4; r++) aF[f][r] = aPrev[f][K2 & 1][r];
                } else {
                    #pragma unroll
                    for (int f = 0; f < 2; f++)
                        ldsm4(aF[f], Pr + swT(rbaseL + f * 16 + rowP, 2 * K2 + cP));
                }
                #pragma unroll
                for (int j = 0; j < 4; j++) {
                    uint32_t vh[4];
                    ldsm4t(vh, bV + swT(K2 * 16 + rowV, 2 * j + cV));
                    #pragma unroll
                    for (int f = 0; f < 2; f++) {
                        mma16816(o[f][2 * j],     aF[f], vh[0], vh[1]);
                        mma16816(o[f][2 * j + 1], aF[f], vh[2], vh[3]);
                    }
                }
            }
        }

        // release stage vS (tile kt-1 fully consumed); producer refills
        if (lane == 0) mbar_arrive(mbE(vS));
        if (kt + 2 < nt) {
            if (tid == 0) { mwait(mbE(vS), pP); issue_tile(kt + 2, vS); }
            if (vS == 2) pP ^= 1;
        }
        softmax_store(s, kt);
        if (++kS == 3) { kS = 0; kP ^= 1; }
    }

    // ---- drain: O += P(nt-1) @ V(nt-1)
    {
        const int vS = (kS == 0) ? 2 : kS - 1;
        const uint32_t bV = sB + (uint32_t)vS * STG_BYTES + 16384 + (uint32_t)colg * 8192;
        const uint32_t Pr = sB + PB_OFF + (uint32_t)((nt - 1) & 1) * 8192;
        #pragma unroll
        for (int K2 = 0; K2 < 4; K2++) {
            uint32_t aF[2][4];
            if ((K2 >> 1) == colg) {
                #pragma unroll
                for (int f = 0; f < 2; f++)
                    #pragma unroll
                    for (int r = 0; r < 4; r++) aF[f][r] = aPrev[f][K2 & 1][r];
            } else {
                #pragma unroll
                for (int f = 0; f < 2; f++)
                    ldsm4(aF[f], Pr + swT(rbaseL + f * 16 + rowP, 2 * K2 + cP));
            }
            #pragma unroll
            for (int j = 0; j < 4; j++) {
                uint32_t vh[4];
                ldsm4t(vh, bV + swT(K2 * 16 + rowV, 2 * j + cV));
                #pragma unroll
                for (int f = 0; f < 2; f++) {
                    mma16816(o[f][2 * j],     aF[f], vh[0], vh[1]);
                    mma16816(o[f][2 * j + 1], aF[f], vh[2], vh[3]);
                }
            }
        }
    }

    // ---- epilogue: reconcile row sums across col-halves, normalize, store
    #pragma unroll
    for (int i = 0; i < 4; i++) {
        l[i] += __shfl_xor_sync(0xffffffffu, l[i], 1);
        l[i] += __shfl_xor_sync(0xffffffffu, l[i], 2);
    }
    float* lbuf = reinterpret_cast<float*>(sm + LB_OFF);
    if (tig == 0) {
        #pragma unroll
        for (int f = 0; f < 2; f++)
            #pragma unroll
            for (int h2 = 0; h2 < 2; h2++)
                lbuf[colg * 64 + rbaseL + f * 16 + h2 * 8 + gid] = l[f * 2 + h2];
    }
    __syncthreads();
    #pragma unroll
    for (int f = 0; f < 2; f++) {
        int lr0 = rbaseL + f * 16 + gid;
        float inv0 = 1.f / (lbuf[lr0] + lbuf[64 + lr0]);
        float inv1 = 1.f / (lbuf[lr0 + 8] + lbuf[64 + lr0 + 8]);
        #pragma unroll
        for (int g = 0; g < 8; g++) {
            int c = colg * 64 + g * 8 + tig * 2;
            float2 w0 = make_float2(o[f][g][0] * inv0, o[f][g][1] * inv0);
            float2 w1 = make_float2(o[f][g][2] * inv1, o[f][g][3] * inv1);
            size_t r0 = (size_t)(q0 + lr0) * (NH * HD) + hh * HD + c;
            size_t r1 = (size_t)(q0 + lr0 + 8) * (NH * HD) + hh * HD + c;
            *reinterpret_cast<float2*>(&out[r0]) = w0;
            *reinterpret_cast<float2*>(&out[r1]) = w1;
        }
    }
}

typedef CUresult (*PFN_encode)(
    CUtensorMap*, CUtensorMapDataType, cuuint32_t, void*,
    const cuuint64_t*, const cuuint64_t*, const cuuint32_t*, const cuuint32_t*,
    CUtensorMapInterleave, CUtensorMapSwizzle, CUtensorMapL2promotion,
    CUtensorMapFloatOOBfill);

extern "C" void kernel_launch(void* const* d_in, const int* in_sizes, int n_in,
                              void* d_out, int out_size) {
    const float* q = (const float*)d_in[0];
    const float* k = (const float*)d_in[1];
    const float* v = (const float*)d_in[2];
    float* out = (float*)d_out;

    const int NK4 = T_TOK * NKV * 32;
    cvt_kernel<<<(2 * NK4 + 255) / 256, 256>>>(k, v);

    PFN_encode encode = nullptr;
    cudaDriverEntryPointQueryResult qres;
    cudaGetDriverEntryPoint("cuTensorMapEncodeTiled", (void**)&encode,
                            cudaEnableDefault, &qres);
    void *pk = nullptr, *pv = nullptr;
    cudaGetSymbolAddress(&pk, gK);
    cudaGetSymbolAddress(&pv, gV);

    CUtensorMap mk, mv;
    cuuint64_t dims[3]    = {HD, T_TOK, NKV};
    cuuint64_t strides[2] = {HD * 2, (cuuint64_t)T_TOK * HD * 2};
    cuuint32_t box[3]     = {64, BN, 1};
    cuuint32_t estr[3]    = {1, 1, 1};
    encode(&mk, CU_TENSOR_MAP_DATA_TYPE_UINT16, 3, pk, dims, strides, box, estr,
           CU_TENSOR_MAP_INTERLEAVE_NONE, CU_TENSOR_MAP_SWIZZLE_128B,
           CU_TENSOR_MAP_L2_PROMOTION_L2_128B, CU_TENSOR_MAP_FLOAT_OOB_FILL_NONE);
    encode(&mv, CU_TENSOR_MAP_DATA_TYPE_UINT16, 3, pv, dims, strides, box, estr,
           CU_TENSOR_MAP_INTERLEAVE_NONE, CU_TENSOR_MAP_SWIZZLE_128B,
           CU_TENSOR_MAP_L2_PROMOTION_L2_128B, CU_TENSOR_MAP_FLOAT_OOB_FILL_NONE);

    cudaFuncSetAttribute(attn_mma_kernel,
                         cudaFuncAttributeMaxDynamicSharedMemorySize, SMEM_BYTES);
    dim3 grid(T_TOK / BM, NH);
    attn_mma_kernel<<<grid, NTH, SMEM_BYTES>>>(mk, mv, q, out);
}